// round 15
// baseline (speedup 1.0000x reference)
#include <cuda_runtime.h>

#define NWARM 365
#define PFD 8   // prefetch depth (register pipeline of future timesteps)

// PARAM_RANGES lo/hi, order: KC,PCTIM,ADIMP,UZTWM,UZFWM,LZTWM,LZFSM,LZFPM,RSERV,
// PFREE,RIVA,ZPERC,REXP,UZK,LZSK,LZPK,CI,CGS,CGP,KE,XE
__constant__ float c_lo[21] = {0.1f, 0.0f, 0.0f, 10.0f, 10.0f, 50.0f, 10.0f, 50.0f,
                               0.0f, 0.0f, 0.0f, 5.0f, 1.0f, 0.1f, 0.01f, 0.001f,
                               0.5f, 0.95f, 0.98f, 0.0f, 0.0f};
__constant__ float c_hi[21] = {1.2f, 0.1f, 0.3f, 100.0f, 100.0f, 400.0f, 100.0f, 1000.0f,
                               0.3f, 0.5f, 0.1f, 350.0f, 4.0f, 0.5f, 0.35f, 0.05f,
                               0.9f, 0.998f, 0.998f, 1.0f, 0.5f};

__device__ __forceinline__ float lg2_approx(float x) {
    float r;
    asm("lg2.approx.f32 %0, %1;" : "=f"(r) : "f"(x));
    return r;
}
__device__ __forceinline__ float ex2_approx(float x) {
    float r;
    asm("ex2.approx.f32 %0, %1;" : "=f"(r) : "f"(x));
    return r;
}

__global__ void __launch_bounds__(128, 1) sac_kernel(
    const float2* __restrict__ pe,      // [T, B] of (prcp, pet)
    const float*  __restrict__ raw,     // [B, 21] raw params in [0.01, 0.99]
    float*        __restrict__ out,     // [2, T-NWARM, B]
    int T, int B)
{
    int b = blockIdx.x * blockDim.x + threadIdx.x;
    if (b >= B) return;

    // ---- load + scale parameters ----
    float pr[21];
#pragma unroll
    for (int i = 0; i < 21; ++i)
        pr[i] = fmaf(raw[b * 21 + i], c_hi[i] - c_lo[i], c_lo[i]);

    const float kc = pr[0],  pctim = pr[1],  adimp = pr[2];
    const float uztwm = pr[3], uzfwm = pr[4], lztwm = pr[5];
    const float lzfsm = pr[6], lzfpm = pr[7];
    const float pfree = pr[9], riva = pr[10];
    const float zperc = pr[11], rexp = pr[12], uzk = pr[13];
    const float lzsk = pr[14], lzpk = pr[15];
    const float ci = pr[16], cgs = pr[17], cgp = pr[18];
    const float ke = pr[19], xe = pr[20];

    // ---- loop-invariant combos ----
    const float inv_uztwm    = 1.0f / uztwm;
    const float inv_sum_utlt = 1.0f / (uztwm + lztwm);
    const float inv_lztwm    = 1.0f / lztwm;
    const float sum_uzm      = uztwm + uzfwm;
    const float pbase        = lzfsm * lzsk + lzfpm * lzpk;
    const float sum_lzm      = lzfsm + lzfpm + lztwm;
    const float sum_lzf      = lzfsm + lzfpm;
    const float cf2          = 2.0f * lzfpm / sum_lzf;
    const float inv_lzfpm    = 1.0f / lzfpm;
    const float inv_lzfsm    = 1.0f / lzfsm;
    const float parea        = 1.0f - pctim - adimp;
    const float omlzsk = 1.0f - lzsk;
    const float omlzpk = 1.0f - lzpk;
    const float gi  = (1.0f - ci)  * parea;
    const float ggs = (1.0f - cgs) * parea;
    const float ggp = (1.0f - cgp) * parea;
    const float c_etep = pctim + riva;          // ae2 + e4 = (pctim+riva)*ep
    const float dtm   = 0.5f;
    const float inv_denom = 1.0f / (ke * (1.0f - xe) + dtm);
    const float c1 = (ke * xe + dtm) * inv_denom;
    const float c2 = (dtm - ke * xe) * inv_denom;
    const float c3 = (ke * (1.0f - xe) - dtm) * inv_denom;
    const float pbase_div_uzfwm = pbase / uzfwm;
    const float omuzk = 1.0f - uzk;   // (unused directly; uf via fmaf below)
    (void)omuzk;
    // exponent folding: zperc*defr^rexp = ex2(rexp*lg2(rate_cap) + powbias)
    const float powbias = lg2_approx(zperc) - rexp * lg2_approx(sum_lzm);

    // ---- state (+ carried normalized copies, maintained off the critical path) ----
    float auztw = 0.01f, alztw = 0.01f, uztw = 0.01f, uzfw = 0.01f, lztw = 0.01f;
    float lzfs = 0.01f, lzfp = 0.01f;
    float qs = 0.01f, qi = 0.01f, qgs = 0.01f, qgp = 0.01f, mq = 0.01f;
    float isum = 0.04f;   // carried i2 of previous step
    float au_n   = auztw * inv_uztwm;
    float alz_n  = alztw * inv_sum_utlt;
    float ut_n   = uztw * inv_uztwm;
    float omut_n = 1.0f - ut_n;         // carried: 1 - uztw/uztwm
    float ltz_n  = lztw * inv_sum_utlt;

    const int TOUT = T - NWARM;
    float* __restrict__ qp  = out + b;                      // running [t][b] in outQ
    float* __restrict__ ep_ = out + (size_t)TOUT * B + b;   // running [t][b] in outE

    // One-step body. New chain cuts vs R13 (all exact or <=2ulp on damped states):
    //  - rate_cap = fmaf(epe12, ltz_n, C0), C0 = (sum_lzm - lzsum) - lztw  (early)
    //  - epa = ep*omut_n; e2 = min(uzfw, epa); epe12 = epa - e2
    //  - uf = fmaf(-uzk, uf0, uf0); ri = uzk*uf0
    //  - percp via distributed min/max: fx-free_s and coef*fx computed straight
    //    from rate in parallel (valid: coef >= 0, min/max distribute over -const)
#define SAC_BODY(PEV, DO_STORE)                                                  \
    {                                                                            \
        /* early: prev-state-only (ready at cycle 0, off critical path) */       \
        float lzsum = lzfs + lzfp;                                               \
        float ca = 1.0f - lzfp * inv_lzfpm;                                      \
        float cb = 1.0f - lzfs * inv_lzfsm;                                      \
        float coef = fminf(cf2 * __fdividef(ca, ca + cb), 1.0f);                 \
        float avail_f = sum_lzf - lzsum;                                         \
        float free_p  = lzfpm - lzfp;                                            \
        float free_s  = lzfsm - lzfs;                                            \
        float m_rc    = sum_lzm - lzsum;                                         \
        float C0      = m_rc - lztw;                                             \
        float amfs    = avail_f - free_s;                                        \
        float cA      = coef * avail_f;                                          \
        float cpf     = coef * pfree;                                            \
        float pre_ls_d = omlzsk * lzfs;                                          \
        float pre_lp_d = omlzpk * lzfp;                                          \
        float pre_ls_r = lzsk * lzfs;                                            \
        float pre_lp_r = lzpk * lzfp;                                            \
        /* input (off carried cycles: load prefetched long ago) */               \
        float p  = fmaxf((PEV).x, 0.0f);                                         \
        float ep = fmaxf(kc * (PEV).y, 0.0f);  /* fmaxf(NaN,0)=0 -> nan_to_num */\
        float roimp = pctim * p;                                                 \
        /* ADIMP store (short cycles) */                                         \
        float ae1 = ep * au_n;                                                   \
        float ae3 = (ep - ae1) * alz_n;                                          \
        float sA  = (auztw - ae1) + p;                                           \
        float pav = fmaxf(sA - uztwm, 0.0f);                                     \
        float alz_ae3 = alztw - ae3;                                             \
        float adsur = pav * (alz_ae3 * inv_lztwm);                               \
        float tmpA = pav - adsur + alz_ae3;                                      \
        float ars = fmaxf(tmpA - lztwm, 0.0f);                                   \
        auztw = fminf(sA, uztwm);                                                \
        alztw = fminf(lztwm, tmpA);                                              \
        au_n  = auztw * inv_uztwm;                                               \
        alz_n = alztw * inv_sum_utlt;                                            \
        /* UZ evap: epa = ep - e1 (one mul off carried omut_n) */                \
        float e1   = ep * ut_n;                                                  \
        float epa  = ep * omut_n;                                                \
        float e2   = fminf(uzfw, epa);                                           \
        float epe12 = epa - e2;             /* = ep - e1 - e2 */                 \
        float e3   = epe12 * ltz_n;                                              \
        float lt1  = lztw - e3;                                                  \
        float e12  = e1 + e2;                                                    \
        float et = (c_etep * ep + (ae1 + ae3)) + (e12 + e3);                     \
        /* UZ balance */                                                         \
        float sU = (uztw - e1) + p;                                              \
        float x  = sU + (uzfw - e2);                                             \
        float rs = fmaxf(x - sum_uzm, 0.0f) * parea;                             \
        float ut = fminf(uztwm, sU);                                             \
        float uf0 = fminf(uzfwm, x - ut);                                        \
        float ri  = uzk * uf0;                                                   \
        float uf  = fmaf(-uzk, uf0, uf0);                                        \
        uztw = ut;                                                               \
        ut_n   = ut * inv_uztwm;                                                 \
        omut_n = 1.0f - ut_n;                                                    \
        /* percolation (critical chain): MUFU starts from fmaf-folded rate_cap */\
        float rate_cap = fmaf(epe12, ltz_n, C0);       /* >= 0 by invariant */   \
        float lg   = lg2_approx(rate_cap);             /* lg2(0)=-inf -> 0 */    \
        float expo = fmaf(rexp, lg, powbias);                                    \
        float tpow = ex2_approx(expo);                                           \
        float Cuf  = pbase_div_uzfwm * uf;                                       \
        float rate = fminf(fmaf(tpow, Cuf, Cuf), rate_cap);                      \
        uzfw = fmaxf(uf - rate, 0.0f);                                           \
        /* mid-step precomputes (parallel with MUFU) */                          \
        float lzlt    = lztwm - lt1;                                             \
        float lzlt_fs = lzlt + free_s;                                           \
        float clzlt   = coef * lzlt;                                             \
        /* distributed percp tree: everything 1-2 links from rate, in parallel */\
        float ga1 = rate - lzlt_fs;                                              \
        float ga2 = fmaf(rate, pfree, -free_s);                                  \
        float t1  = fminf(amfs, fmaxf(ga1, ga2));      /* = fx - free_s */       \
        float gb1 = fmaf(coef, rate, -clzlt);                                    \
        float gb2 = cpf * rate;                                                  \
        float t2  = fminf(cA, fmaxf(gb1, gb2));        /* = coef * fx   */       \
        float percp = fminf(free_p, fmaxf(t1, t2));                              \
        float fx = fminf(avail_f, fmaxf(rate - lzlt, rate * pfree));             \
        float percs = fx - percp;                                                \
        float perct = rate - fx;                                                 \
        /* LZ update + decay (folded) */                                         \
        float lt = fminf(lt1 + perct, lztwm);                                    \
        lztw  = lt;                                                              \
        ltz_n = lt * inv_sum_utlt;                                               \
        lzfs = fmaf(omlzsk, percs, pre_ls_d);                                    \
        lzfp = fmaf(omlzpk, percp, pre_lp_d);                                    \
        float rgs = fmaf(lzsk, percs, pre_ls_r);                                 \
        float rgp = fmaf(lzpk, percp, pre_lp_r);                                 \
        /* routing (short, off-chain) */                                         \
        float i1 = isum;                                                         \
        qs  = (roimp + rs) + (adsur + ars) * adimp;                              \
        qi  = ci  * qi  + gi  * ri;                                              \
        qgs = cgs * qgs + ggs * rgs;                                             \
        qgp = cgp * qgp + ggp * rgp;                                             \
        float i2 = (qs + qi) + (qgs + qgp);                                      \
        isum = i2;                                                               \
        float o2 = c1 * i1 + (c2 * i2 + c3 * mq);                                \
        mq = o2;                                                                 \
        if (DO_STORE) {                                                          \
            __stcs(qp, o2);                                                      \
            __stcs(ep_, et);                                                     \
            qp += B; ep_ += B;                                                   \
        }                                                                        \
    }

    // ---- register pipeline: PFD timesteps in flight ----
    float2 buf[PFD];
#pragma unroll
    for (int d = 0; d < PFD; ++d) {
        int idx = d < T ? d : T - 1;
        buf[d] = __ldcs(&pe[(size_t)idx * B + b]);
    }
    const float2* __restrict__ pload = pe + (size_t)PFD * B + b;
    const size_t strideB = B;

    // ---- warmup phase: t in [0, NWARM), no stores ----
    int t = 0;
    for (; t + PFD <= NWARM; t += PFD) {
#pragma unroll
        for (int j = 0; j < PFD; ++j) {
            float2 nxt = __ldcs(pload); pload += strideB;
            SAC_BODY(buf[j], false);
            buf[j] = nxt;
        }
    }
    {
        int rem = NWARM - t;   // 365 = 45*8+5 -> rem=5
#pragma unroll
        for (int j = 0; j < PFD; ++j) {
            if (j < rem) {
                float2 nxt = __ldcs(pload); pload += strideB;
                SAC_BODY(buf[j], false);
                buf[j] = nxt;
            }
        }
        float2 tmp[PFD];
#pragma unroll
        for (int j = 0; j < PFD; ++j) {
            int src = j + rem;
            tmp[j] = buf[src < PFD ? src : src - PFD];
        }
#pragma unroll
        for (int j = 0; j < PFD; ++j) buf[j] = tmp[j];
        t = NWARM;
    }

    // ---- output phase main: loads unconditionally valid while t+2*PFD <= T ----
    for (; t + 2 * PFD <= T; t += PFD) {
#pragma unroll
        for (int j = 0; j < PFD; ++j) {
            float2 nxt = __ldcs(pload); pload += strideB;
            SAC_BODY(buf[j], true);
            buf[j] = nxt;
        }
    }
    // penultimate chunk(s): clamped loads
    for (; t + PFD <= T; t += PFD) {
#pragma unroll
        for (int j = 0; j < PFD; ++j) {
            int tl = t + j + PFD;
            float2 nxt = __ldcs(&pe[(size_t)(tl < T ? tl : T - 1) * B + b]);
            SAC_BODY(buf[j], true);
            buf[j] = nxt;
        }
    }
    // guarded tail (< PFD steps)
#pragma unroll
    for (int j = 0; j < PFD; ++j) {
        if (t + j < T) {
            SAC_BODY(buf[j], true);
        }
    }
#undef SAC_BODY
}

extern "C" void kernel_launch(void* const* d_in, const int* in_sizes, int n_in,
                              void* d_out, int out_size) {
    const float* pe     = (const float*)d_in[0];   // [T, B, 2] f32
    const float* params = (const float*)d_in[1];   // [B, 21]  f32
    int B = in_sizes[1] / 21;
    int T = in_sizes[0] / (2 * B);
    int threads = 128;
    int blocks = (B + threads - 1) / threads;
    sac_kernel<<<blocks, threads>>>((const float2*)pe, params, (float*)d_out, T, B);
}